// round 12
// baseline (speedup 1.0000x reference)
#include <cuda_runtime.h>
#include <cstdint>
#include <cstddef>

#define NUM_USERS 10000
#define EMBED_DIM 64
#define BATCH     4096
#define TM        128            // b rows per CTA
#define CK        64             // u per chunk (K per stage)
#define SPLITS    9
#define NCH       157            // ceil(10000/64)
#define NTILES    (BATCH / TM)   // 32

// smem: A = raw fp32 W tile [128][68f pitch]; B = fragment-major tf32 tile (16KB)
#define A_PITCH_B 272            // 68 floats/row -> conflict-free ldmatrix rows
#define OFF_A     0
#define A_BYTES   (TM * A_PITCH_B)        // 34816
#define OFF_B     A_BYTES
#define B_BYTES   16384                   // 8ks x 4q x 32lanes x 16B
#define BUF_STRIDE (A_BYTES + B_BYTES)    // 51200
#define DSM_SIZE  (2 * BUF_STRIDE)        // 102400

// Precomputed E in tf32, FRAGMENT-MAJOR: [chunk][ks][q][lane] -> 16B
//   lane: tig=lane&3, g=lane>>2;  k0=ks*8+tig;  n0=(2q)*8+g; n1=n0+8
//   words = { B(k0,n0), B(k0+4,n0), B(k0,n1), B(k0+4,n1) }
__device__ __align__(16) uint32_t g_Bf[NCH * 1024 * 4];
__device__ float        g_partials[SPLITS][BATCH];
__device__ unsigned int g_cnt[NTILES];

// ---------------- helpers ----------------
__device__ __forceinline__ uint32_t smem_u32(const void* p) {
    uint32_t a;
    asm("{ .reg .u64 t; cvta.to.shared.u64 t, %1; cvt.u32.u64 %0, t; }" : "=r"(a) : "l"(p));
    return a;
}
__device__ __forceinline__ uint32_t f2tf(float f) {
    uint32_t r;
    asm("cvt.rna.tf32.f32 %0, %1;" : "=r"(r) : "f"(f));
    return r;
}
__device__ __forceinline__ void lds128(uint4& v, uint32_t a) {
    asm volatile("ld.shared.v4.b32 {%0,%1,%2,%3}, [%4];"
        : "=r"(v.x), "=r"(v.y), "=r"(v.z), "=r"(v.w) : "r"(a));
}
__device__ __forceinline__ void ldsm_x4(uint32_t* r, uint32_t a) {
    asm volatile("ldmatrix.sync.aligned.m8n8.x4.shared.b16 {%0,%1,%2,%3}, [%4];"
        : "=r"(r[0]), "=r"(r[1]), "=r"(r[2]), "=r"(r[3]) : "r"(a));
}
__device__ __forceinline__ void cp_async16(uint32_t dst, const void* src) {
    asm volatile("{ .reg .u64 g; cvta.to.global.u64 g, %1; cp.async.cg.shared.global [%0], [g], 16; }"
        :: "r"(dst), "l"(src));
}
__device__ __forceinline__ void cp_async16z(uint32_t dst, const void* src, uint32_t sz) {
    asm volatile("{ .reg .u64 g; cvta.to.global.u64 g, %1; cp.async.cg.shared.global [%0], [g], 16, %2; }"
        :: "r"(dst), "l"(src), "r"(sz));
}
#define CP_COMMIT() asm volatile("cp.async.commit_group;" ::: "memory")
#define CP_WAIT0()  asm volatile("cp.async.wait_group 0;" ::: "memory")

__device__ __forceinline__ void mma_tf32(float4& c, const uint32_t* a, uint32_t b0, uint32_t b1) {
    asm volatile(
        "mma.sync.aligned.m16n8k8.row.col.f32.tf32.tf32.f32 "
        "{%0,%1,%2,%3}, {%4,%5,%6,%7}, {%8,%9}, {%0,%1,%2,%3};"
        : "+f"(c.x), "+f"(c.y), "+f"(c.z), "+f"(c.w)
        : "r"(a[0]), "r"(a[1]), "r"(a[2]), "r"(a[3]), "r"(b0), "r"(b1));
}

// Index dtype sniff: int64 iff all sampled high words are zero.
__device__ __forceinline__ int sniff_is64(const void* items_raw, int tid) {
    const unsigned int* iw = (const unsigned int*)items_raw;
    int any = (tid < 256) ? (iw[2 * tid + 1] != 0u) : 0;
    return __syncthreads_or(any) == 0;
}
__device__ __forceinline__ int load_idx(const void* raw, int i, int is64) {
    return is64 ? (int)((const long long*)raw)[i] : ((const int*)raw)[i];
}

// ---------------- setup: E -> tf32 fragment-major image ----------------
__global__ void setup_b_kernel(const float* __restrict__ user_emb) {
    __shared__ float sE[64 * 65];
    const int c = blockIdx.x;           // chunk 0..156
    const int t = threadIdx.x;

    #pragma unroll
    for (int i = 0; i < 4; i++) {
        int idx = t + i * 256;          // 0..1023
        int row = idx >> 4;             // u local (k)
        int q4  = idx & 15;
        int u   = c * CK + row;
        float4 v = (u < NUM_USERS) ? *(const float4*)&user_emb[(size_t)u * EMBED_DIM + q4 * 4]
                                   : make_float4(0.f, 0.f, 0.f, 0.f);
        sE[row * 65 + q4 * 4 + 0] = v.x;
        sE[row * 65 + q4 * 4 + 1] = v.y;
        sE[row * 65 + q4 * 4 + 2] = v.z;
        sE[row * 65 + q4 * 4 + 3] = v.w;
    }
    __syncthreads();
    #pragma unroll
    for (int i = 0; i < 4; i++) {
        int idx  = t + i * 256;         // (ks,q,lane) linear
        int lane = idx & 31;
        int q    = (idx >> 5) & 3;
        int ks   = idx >> 7;
        int tig  = lane & 3, g = lane >> 2;
        int k0 = ks * 8 + tig;
        int n0 = (2 * q) * 8 + g;
        uint4 w;
        w.x = f2tf(sE[k0 * 65 + n0]);
        w.y = f2tf(sE[(k0 + 4) * 65 + n0]);
        w.z = f2tf(sE[k0 * 65 + n0 + 8]);
        w.w = f2tf(sE[(k0 + 4) * 65 + n0 + 8]);
        *(uint4*)&g_Bf[((size_t)c * 1024 + idx) * 4] = w;
    }
}

// ---------------- fused kernel ----------------
__global__ __launch_bounds__(256, 2)
void bpr_kernel(const float* __restrict__ user_emb,
                const float* __restrict__ item_emb,
                const float* __restrict__ social,
                const void*  __restrict__ users_raw,
                const void*  __restrict__ items_raw,
                float* __restrict__ out)
{
    extern __shared__ __align__(16) char dsm[];
    __shared__ int sU[TM];
    __shared__ int sI[TM];
    __shared__ unsigned int s_old;

    const uint32_t sb  = smem_u32(dsm);
    const int tid  = threadIdx.x;
    const int wid  = tid >> 5;
    const int lane = tid & 31;
    const int b0    = blockIdx.x * TM;
    const int split = blockIdx.y;

    const int is64 = sniff_is64(items_raw, tid);
    if (tid < TM) {
        sU[tid] = load_idx(users_raw, b0 + tid, is64);
        sI[tid] = load_idx(items_raw, b0 + tid, is64);
    }
    __syncthreads();

    // ---- A staging: thread covers rows strow+16p, 16B segment scol16 ----
    const int strow  = tid >> 4;         // 0..15
    const int scol16 = tid & 15;
    const float* aSrc[8];
    #pragma unroll
    for (int p = 0; p < 8; p++)
        aSrc[p] = social + (size_t)sU[strow + p * 16] * NUM_USERS + scol16 * 4;

    // ---- fragment geometry ----
    // ldmatrix x4 lane address: row = wid*16 + (lane&15), col-half = (lane>>4)*16B
    const uint32_t aLdsmOff = (uint32_t)((wid * 16 + (lane & 15)) * A_PITCH_B + (lane >> 4) * 16);
    const uint32_t bLaneOff = (uint32_t)(lane * 16);

    float4 acc[8];
    #pragma unroll
    for (int n = 0; n < 8; n++) acc[n] = make_float4(0.f, 0.f, 0.f, 0.f);

    // ---- prologue: stage chunk `split` into buf 0 ----
    {
        const int u0   = split * CK;
        const int colu = u0 + scol16 * 4;
        uint32_t sz = (colu < NUM_USERS) ? 16u : 0u;   // 10000 % 4 == 0
        #pragma unroll
        for (int p = 0; p < 8; p++)
            cp_async16z(sb + OFF_A + (uint32_t)((strow + p * 16) * A_PITCH_B + scol16 * 16),
                        aSrc[p] + u0, sz);
        #pragma unroll
        for (int p = 0; p < 4; p++) {
            uint32_t idx = (uint32_t)(tid + p * 256);
            cp_async16(sb + OFF_B + idx * 16, g_Bf + ((size_t)split * 1024 + idx) * 4);
        }
        CP_COMMIT();
        CP_WAIT0();
    }
    __syncthreads();

    // ---- mainloop ----
    int buf = 0;
    for (int c = split; c < NCH; c += SPLITS) {
        const int cn = c + SPLITS;
        const bool more = (cn < NCH);

        // stage next chunk into other buffer (async, overlaps compute)
        if (more) {
            const uint32_t bo = (uint32_t)(buf ? 0 : BUF_STRIDE);
            const int u0   = cn * CK;
            const int colu = u0 + scol16 * 4;
            uint32_t sz = (colu < NUM_USERS) ? 16u : 0u;
            #pragma unroll
            for (int p = 0; p < 8; p++)
                cp_async16z(sb + bo + OFF_A + (uint32_t)((strow + p * 16) * A_PITCH_B + scol16 * 16),
                            aSrc[p] + u0, sz);
            #pragma unroll
            for (int p = 0; p < 4; p++) {
                uint32_t idx = (uint32_t)(tid + p * 256);
                cp_async16(sb + bo + OFF_B + idx * 16, g_Bf + ((size_t)cn * 1024 + idx) * 4);
            }
            CP_COMMIT();
        }

        // compute on current buffer: per ks = 1 ldmatrix + 4 cvt + 4 LDS.128 + 8 MMA
        {
            const uint32_t bo = (uint32_t)(buf ? BUF_STRIDE : 0);
            const uint32_t aB = sb + bo + OFF_A + aLdsmOff;
            const uint32_t bB = sb + bo + OFF_B + bLaneOff;
            #pragma unroll
            for (int ks = 0; ks < 8; ks++) {
                uint32_t ar[4];
                ldsm_x4(ar, aB + (uint32_t)(ks * 32));
                uint32_t a[4];
                a[0] = f2tf(__uint_as_float(ar[0]));
                a[1] = f2tf(__uint_as_float(ar[1]));
                a[2] = f2tf(__uint_as_float(ar[2]));
                a[3] = f2tf(__uint_as_float(ar[3]));
                #pragma unroll
                for (int q = 0; q < 4; q++) {
                    uint4 w;
                    lds128(w, bB + (uint32_t)((ks * 4 + q) * 512));
                    mma_tf32(acc[2 * q],     a, w.x, w.y);
                    mma_tf32(acc[2 * q + 1], a, w.z, w.w);
                }
            }
        }

        if (more) CP_WAIT0();
        __syncthreads();
        buf ^= 1;
    }

    // ---- epilogue: dot with bi, reduce across 4 lanes per row ----
    {
        const int r0 = wid * 16 + (lane >> 2);
        const int r1 = r0 + 8;
        const float* ip0 = item_emb + (size_t)sI[r0] * EMBED_DIM;
        const float* ip1 = item_emb + (size_t)sI[r1] * EMBED_DIM;
        const int cbase = (lane & 3) * 2;
        float v0 = 0.f, v1 = 0.f;
        #pragma unroll
        for (int n = 0; n < 8; n++) {
            const int cn = n * 8 + cbase;
            float2 e0 = *(const float2*)(ip0 + cn);
            float2 e1 = *(const float2*)(ip1 + cn);
            v0 += acc[n].x * e0.x + acc[n].y * e0.y;
            v1 += acc[n].z * e1.x + acc[n].w * e1.y;
        }
        v0 += __shfl_xor_sync(0xffffffffu, v0, 1);
        v0 += __shfl_xor_sync(0xffffffffu, v0, 2);
        v1 += __shfl_xor_sync(0xffffffffu, v1, 1);
        v1 += __shfl_xor_sync(0xffffffffu, v1, 2);
        if ((lane & 3) == 0) {
            g_partials[split][b0 + r0] = v0;
            g_partials[split][b0 + r1] = v1;
        }
    }
    __syncthreads();

    // ---- last split for this b-tile: fixed-order sum + pos term (deterministic) ----
    if (tid == 0) {
        __threadfence();
        s_old = atomicAdd(&g_cnt[blockIdx.x], 1u);
    }
    __syncthreads();
    if (s_old == SPLITS - 1) {
        __threadfence();
        if (tid < TM) {
            const int b = b0 + tid;
            float s = 0.f;
            #pragma unroll
            for (int p = 0; p < SPLITS; p++) s += g_partials[p][b];
            const float4* ue = (const float4*)(user_emb + (size_t)sU[tid] * EMBED_DIM);
            const float4* ie = (const float4*)(item_emb + (size_t)sI[tid] * EMBED_DIM);
            float d = 0.f;
            #pragma unroll
            for (int k = 0; k < 16; k++) {
                float4 a = ue[k], c2 = ie[k];
                d += a.x * c2.x + a.y * c2.y + a.z * c2.z + a.w * c2.w;
            }
            out[b] = s + d;
        }
        __syncthreads();
        if (tid == 0) g_cnt[blockIdx.x] = 0u;   // self-reset for graph replay
    }
}

extern "C" void kernel_launch(void* const* d_in, const int* in_sizes, int n_in,
                              void* d_out, int out_size)
{
    const float* user_emb = (const float*)d_in[0];   // [10000, 64]
    const float* item_emb = (const float*)d_in[1];   // [100000, 64]
    const float* social   = (const float*)d_in[2];   // [10000, 10000]
    const void*  users    = d_in[3];                 // [4096] idx
    const void*  items    = d_in[4];                 // [4096] idx

    cudaFuncSetAttribute((const void*)bpr_kernel,
                         cudaFuncAttributeMaxDynamicSharedMemorySize, DSM_SIZE);

    setup_b_kernel<<<NCH, 256>>>(user_emb);

    dim3 grid(NTILES, SPLITS);   // 32 x 9 = 288 CTAs, one wave @ occ 2
    bpr_kernel<<<grid, 256, DSM_SIZE>>>(user_emb, item_emb, social, users, items, (float*)d_out);
}

// round 14
// speedup vs baseline: 1.4077x; 1.4077x over previous
#include <cuda_runtime.h>
#include <cstdint>
#include <cstddef>

#define NUM_USERS 10000
#define EMBED_DIM 64
#define BATCH     4096
#define TM        128            // b rows per CTA
#define CK        64             // u per chunk (K per stage)
#define SPLITS    9
#define NCH       157            // ceil(10000/64)
#define NTILES    (BATCH / TM)   // 32

// smem: A = raw fp32 W tile [128][68f pitch]; B = fragment-major tf32 tile (16KB)
#define A_PITCH_B 272            // 68 floats/row: bank = 4r+k -> conflict-free A frags
#define OFF_A     0
#define A_BYTES   (TM * A_PITCH_B)        // 34816
#define OFF_B     A_BYTES
#define B_BYTES   16384                   // 8ks x 4q x 32lanes x 16B
#define BUF_STRIDE (A_BYTES + B_BYTES)    // 51200
#define DSM_SIZE  (2 * BUF_STRIDE)        // 102400

// Precomputed E in tf32, FRAGMENT-MAJOR: [chunk][ks][q][lane] -> 16B
//   lane: tig=lane&3, g=lane>>2;  k0=ks*8+tig;  n0=(2q)*8+g; n1=n0+8
//   words = { B(k0,n0), B(k0+4,n0), B(k0,n1), B(k0+4,n1) }
__device__ __align__(16) uint32_t g_Bf[NCH * 1024 * 4];
__device__ float        g_partials[SPLITS][BATCH];
__device__ unsigned int g_cnt[NTILES];

// ---------------- helpers ----------------
__device__ __forceinline__ uint32_t smem_u32(const void* p) {
    uint32_t a;
    asm("{ .reg .u64 t; cvta.to.shared.u64 t, %1; cvt.u32.u64 %0, t; }" : "=r"(a) : "l"(p));
    return a;
}
__device__ __forceinline__ uint32_t f2tf(float f) {
    uint32_t r;
    asm("cvt.rna.tf32.f32 %0, %1;" : "=r"(r) : "f"(f));
    return r;
}
__device__ __forceinline__ void lds_f32(float& d, uint32_t a) {
    asm volatile("ld.shared.f32 %0, [%1];" : "=f"(d) : "r"(a));
}
__device__ __forceinline__ void lds128(uint4& v, uint32_t a) {
    asm volatile("ld.shared.v4.b32 {%0,%1,%2,%3}, [%4];"
        : "=r"(v.x), "=r"(v.y), "=r"(v.z), "=r"(v.w) : "r"(a));
}
__device__ __forceinline__ void cp_async16(uint32_t dst, const void* src) {
    asm volatile("{ .reg .u64 g; cvta.to.global.u64 g, %1; cp.async.cg.shared.global [%0], [g], 16; }"
        :: "r"(dst), "l"(src));
}
__device__ __forceinline__ void cp_async16z(uint32_t dst, const void* src, uint32_t sz) {
    asm volatile("{ .reg .u64 g; cvta.to.global.u64 g, %1; cp.async.cg.shared.global [%0], [g], 16, %2; }"
        :: "r"(dst), "l"(src), "r"(sz));
}
#define CP_COMMIT() asm volatile("cp.async.commit_group;" ::: "memory")
#define CP_WAIT0()  asm volatile("cp.async.wait_group 0;" ::: "memory")

__device__ __forceinline__ void mma_tf32(float4& c, const uint32_t* a, uint32_t b0, uint32_t b1) {
    asm volatile(
        "mma.sync.aligned.m16n8k8.row.col.f32.tf32.tf32.f32 "
        "{%0,%1,%2,%3}, {%4,%5,%6,%7}, {%8,%9}, {%0,%1,%2,%3};"
        : "+f"(c.x), "+f"(c.y), "+f"(c.z), "+f"(c.w)
        : "r"(a[0]), "r"(a[1]), "r"(a[2]), "r"(a[3]), "r"(b0), "r"(b1));
}

// Index dtype sniff: int64 iff all sampled high words are zero.
__device__ __forceinline__ int sniff_is64(const void* items_raw, int tid) {
    const unsigned int* iw = (const unsigned int*)items_raw;
    int any = (tid < 256) ? (iw[2 * tid + 1] != 0u) : 0;
    return __syncthreads_or(any) == 0;
}
__device__ __forceinline__ int load_idx(const void* raw, int i, int is64) {
    return is64 ? (int)((const long long*)raw)[i] : ((const int*)raw)[i];
}

// ---------------- setup: E -> tf32 fragment-major image ----------------
__global__ void setup_b_kernel(const float* __restrict__ user_emb) {
    __shared__ float sE[64 * 65];
    const int c = blockIdx.x;           // chunk 0..156
    const int t = threadIdx.x;

    #pragma unroll
    for (int i = 0; i < 4; i++) {
        int idx = t + i * 256;          // 0..1023
        int row = idx >> 4;             // u local (k)
        int q4  = idx & 15;
        int u   = c * CK + row;
        float4 v = (u < NUM_USERS) ? *(const float4*)&user_emb[(size_t)u * EMBED_DIM + q4 * 4]
                                   : make_float4(0.f, 0.f, 0.f, 0.f);
        sE[row * 65 + q4 * 4 + 0] = v.x;
        sE[row * 65 + q4 * 4 + 1] = v.y;
        sE[row * 65 + q4 * 4 + 2] = v.z;
        sE[row * 65 + q4 * 4 + 3] = v.w;
    }
    __syncthreads();
    #pragma unroll
    for (int i = 0; i < 4; i++) {
        int idx  = t + i * 256;         // (ks,q,lane) linear
        int lane = idx & 31;
        int q    = (idx >> 5) & 3;
        int ks   = idx >> 7;
        int tig  = lane & 3, g = lane >> 2;
        int k0 = ks * 8 + tig;
        int n0 = (2 * q) * 8 + g;
        uint4 w;
        w.x = f2tf(sE[k0 * 65 + n0]);
        w.y = f2tf(sE[(k0 + 4) * 65 + n0]);
        w.z = f2tf(sE[k0 * 65 + n0 + 8]);
        w.w = f2tf(sE[(k0 + 4) * 65 + n0 + 8]);
        *(uint4*)&g_Bf[((size_t)c * 1024 + idx) * 4] = w;
    }
}

// ---------------- fused kernel: tf32 single pass; A scalar frags, B vector frags ----------------
__global__ __launch_bounds__(256, 2)
void bpr_kernel(const float* __restrict__ user_emb,
                const float* __restrict__ item_emb,
                const float* __restrict__ social,
                const void*  __restrict__ users_raw,
                const void*  __restrict__ items_raw,
                float* __restrict__ out)
{
    extern __shared__ __align__(16) char dsm[];
    __shared__ int sU[TM];
    __shared__ int sI[TM];
    __shared__ unsigned int s_old;

    const uint32_t sb  = smem_u32(dsm);
    const int tid  = threadIdx.x;
    const int wid  = tid >> 5;
    const int lane = tid & 31;
    const int b0    = blockIdx.x * TM;
    const int split = blockIdx.y;

    const int is64 = sniff_is64(items_raw, tid);
    if (tid < TM) {
        sU[tid] = load_idx(users_raw, b0 + tid, is64);
        sI[tid] = load_idx(items_raw, b0 + tid, is64);
    }
    __syncthreads();

    // ---- A staging: thread covers rows strow+16p, 16B segment scol16 (coalesced 256B rows) ----
    const int strow  = tid >> 4;         // 0..15
    const int scol16 = tid & 15;
    const float* aSrc[8];
    #pragma unroll
    for (int p = 0; p < 8; p++)
        aSrc[p] = social + (size_t)sU[strow + p * 16] * NUM_USERS + scol16 * 4;

    // ---- fragment geometry (per lane) ----
    const uint32_t aFragBase = (uint32_t)((wid * 16 + (lane >> 2)) * A_PITCH_B + (lane & 3) * 4);
    const uint32_t bLaneOff  = (uint32_t)(lane * 16);

    float4 acc[8];
    #pragma unroll
    for (int n = 0; n < 8; n++) acc[n] = make_float4(0.f, 0.f, 0.f, 0.f);

    // ---- prologue: stage chunk `split` into buf 0 ----
    {
        const int u0   = split * CK;
        const int colu = u0 + scol16 * 4;
        uint32_t sz = (colu < NUM_USERS) ? 16u : 0u;   // 10000 % 4 == 0
        #pragma unroll
        for (int p = 0; p < 8; p++)
            cp_async16z(sb + OFF_A + (uint32_t)((strow + p * 16) * A_PITCH_B + scol16 * 16),
                        aSrc[p] + u0, sz);
        #pragma unroll
        for (int p = 0; p < 4; p++) {
            uint32_t idx = (uint32_t)(tid + p * 256);
            cp_async16(sb + OFF_B + idx * 16, g_Bf + ((size_t)split * 1024 + idx) * 4);
        }
        CP_COMMIT();
        CP_WAIT0();
    }
    __syncthreads();

    // ---- mainloop ----
    int buf = 0;
    for (int c = split; c < NCH; c += SPLITS) {
        const int cn = c + SPLITS;
        const bool more = (cn < NCH);

        // stage next chunk into other buffer (async, overlaps compute)
        if (more) {
            const uint32_t bo = (uint32_t)(buf ? 0 : BUF_STRIDE);
            const int u0   = cn * CK;
            const int colu = u0 + scol16 * 4;
            uint32_t sz = (colu < NUM_USERS) ? 16u : 0u;
            #pragma unroll
            for (int p = 0; p < 8; p++)
                cp_async16z(sb + bo + OFF_A + (uint32_t)((strow + p * 16) * A_PITCH_B + scol16 * 16),
                            aSrc[p] + u0, sz);
            #pragma unroll
            for (int p = 0; p < 4; p++) {
                uint32_t idx = (uint32_t)(tid + p * 256);
                cp_async16(sb + bo + OFF_B + idx * 16, g_Bf + ((size_t)cn * 1024 + idx) * 4);
            }
            CP_COMMIT();
        }

        // compute: per ks = 4 scalar LDS (independent) + 4 cvt + 4 LDS.128 + 8 MMA
        {
            const uint32_t bo = (uint32_t)(buf ? BUF_STRIDE : 0);
            const uint32_t aB = sb + bo + OFF_A + aFragBase;
            const uint32_t bB = sb + bo + OFF_B + bLaneOff;
            #pragma unroll
            for (int ks = 0; ks < 8; ks++) {
                float f0, f1, f2, f3;
                const uint32_t ka = aB + (uint32_t)(ks * 32);
                lds_f32(f0, ka);
                lds_f32(f1, ka + 8 * A_PITCH_B);
                lds_f32(f2, ka + 16);
                lds_f32(f3, ka + 16 + 8 * A_PITCH_B);
                uint32_t a[4] = { f2tf(f0), f2tf(f1), f2tf(f2), f2tf(f3) };
                #pragma unroll
                for (int q = 0; q < 4; q++) {
                    uint4 w;
                    lds128(w, bB + (uint32_t)((ks * 4 + q) * 512));
                    mma_tf32(acc[2 * q],     a, w.x, w.y);
                    mma_tf32(acc[2 * q + 1], a, w.z, w.w);
                }
            }
        }

        if (more) CP_WAIT0();
        __syncthreads();
        buf ^= 1;
    }

    // ---- epilogue: dot with bi, reduce across 4 lanes per row ----
    {
        const int r0 = wid * 16 + (lane >> 2);
        const int r1 = r0 + 8;
        const float* ip0 = item_emb + (size_t)sI[r0] * EMBED_DIM;
        const float* ip1 = item_emb + (size_t)sI[r1] * EMBED_DIM;
        const int cbase = (lane & 3) * 2;
        float v0 = 0.f, v1 = 0.f;
        #pragma unroll
        for (int n = 0; n < 8; n++) {
            const int cn = n * 8 + cbase;
            float2 e0 = *(const float2*)(ip0 + cn);
            float2 e1 = *(const float2*)(ip1 + cn);
            v0 += acc[n].x * e0.x + acc[n].y * e0.y;
            v1 += acc[n].z * e1.x + acc[n].w * e1.y;
        }
        v0 += __shfl_xor_sync(0xffffffffu, v0, 1);
        v0 += __shfl_xor_sync(0xffffffffu, v0, 2);
        v1 += __shfl_xor_sync(0xffffffffu, v1, 1);
        v1 += __shfl_xor_sync(0xffffffffu, v1, 2);
        if ((lane & 3) == 0) {
            g_partials[split][b0 + r0] = v0;
            g_partials[split][b0 + r1] = v1;
        }
    }
    __syncthreads();

    // ---- last split for this b-tile: fixed-order sum + pos term (deterministic) ----
    if (tid == 0) {
        __threadfence();
        s_old = atomicAdd(&g_cnt[blockIdx.x], 1u);
    }
    __syncthreads();
    if (s_old == SPLITS - 1) {
        __threadfence();
        if (tid < TM) {
            const int b = b0 + tid;
            float s = 0.f;
            #pragma unroll
            for (int p = 0; p < SPLITS; p++) s += g_partials[p][b];
            const float4* ue = (const float4*)(user_emb + (size_t)sU[tid] * EMBED_DIM);
            const float4* ie = (const float4*)(item_emb + (size_t)sI[tid] * EMBED_DIM);
            float d = 0.f;
            #pragma unroll
            for (int k = 0; k < 16; k++) {
                float4 a = ue[k], c2 = ie[k];
                d += a.x * c2.x + a.y * c2.y + a.z * c2.z + a.w * c2.w;
            }
            out[b] = s + d;
        }
        __syncthreads();
        if (tid == 0) g_cnt[blockIdx.x] = 0u;   // self-reset for graph replay
    }
}

extern "C" void kernel_launch(void* const* d_in, const int* in_sizes, int n_in,
                              void* d_out, int out_size)
{
    const float* user_emb = (const float*)d_in[0];   // [10000, 64]
    const float* item_emb = (const float*)d_in[1];   // [100000, 64]
    const float* social   = (const float*)d_in[2];   // [10000, 10000]
    const void*  users    = d_in[3];                 // [4096] idx
    const void*  items    = d_in[4];                 // [4096] idx

    cudaFuncSetAttribute((const void*)bpr_kernel,
                         cudaFuncAttributeMaxDynamicSharedMemorySize, DSM_SIZE);

    setup_b_kernel<<<NCH, 256>>>(user_emb);

    dim3 grid(NTILES, SPLITS);   // 32 x 9 = 288 CTAs, one wave @ occ 2
    bpr_kernel<<<grid, 256, DSM_SIZE>>>(user_emb, item_emb, social, users, items, (float*)d_out);
}